// round 17
// baseline (speedup 1.0000x reference)
#include <cuda_runtime.h>
#include <cstdint>

// out[b,i,j,c] = sum_k exp(-2(li-x0k)^2)*exp(-2(lj-x1k)^2)*Yb[k,c]
// GEMM: C[64 x 640] = A[64 x 1024] * Z[1024 x 640], bf16 mma m16n8k16.
// SINGLE fused kernel: phase0 A-frag gen (1/256 slice per CTA) -> soft grid
// barrier (all 256 CTAs co-resident at 2 CTAs/SM) overlapped by phase1 Z-build.
#define NB    16
#define NN    1024
#define STEP  (6.0f / 63.0f)
#define EX2C  (-2.885390081777927f)   // -2*log2(e)

// A frags: u32 idx = b*32768 + kstep*512 + slab*128 + lane*4 + q
__device__ __align__(16) uint32_t g_Aperm[NB * 64 * 4 * 32 * 4];
__device__ int g_arrive = 0;
__device__ int g_done   = 0;

__device__ __forceinline__ float ex2f(float x) {
    float r; asm("ex2.approx.ftz.f32 %0, %1;" : "=f"(r) : "f"(x)); return r;
}
__device__ __forceinline__ uint32_t pack_bf16(float lo, float hi) {
    uint32_t d;
    asm("cvt.rn.bf16x2.f32 %0, %1, %2;" : "=r"(d) : "f"(hi), "f"(lo));
    return d;
}
#define MMA_BF16(d, a, bb) \
    asm volatile("mma.sync.aligned.m16n8k16.row.col.f32.bf16.bf16.f32 " \
        "{%0,%1,%2,%3}, {%4,%5,%6,%7}, {%8,%9}, {%0,%1,%2,%3};" \
        : "+f"(d[0]), "+f"(d[1]), "+f"(d[2]), "+f"(d[3]) \
        : "r"(a.x), "r"(a.y), "r"(a.z), "r"(a.w), "r"(bb.x), "r"(bb.y))

#define ZSLOTS (64 * 5 * 32)      // 10240 uint2 = 81920 B

__global__ __launch_bounds__(512, 2)
void rkhs_fused_kernel(const float* __restrict__ X, const float* __restrict__ Y,
                       float* __restrict__ out)
{
    extern __shared__ __align__(16) uint2 sZ[];   // [kstep*5+nc][32]

    const int bx = blockIdx.x;
    const int jt = bx & 15;
    const int b  = bx >> 4;
    const int t  = threadIdx.x;

    const int ks = t >> 8;            // K-group 0/1
    const int tl = t & 255;

    // ===== Phase 0: this CTA's 1/256 slice of A frags (1 uint4/thread) =====
    {
        int flat = bx * 512 + t;              // uint4 index, 131072 total
        int lane  = flat & 31;
        int slab  = (flat >> 5) & 3;
        int kstep = (flat >> 7) & 63;
        int ab    = flat >> 13;               // A's batch (not this CTA's b)
        int kb    = kstep * 16 + (lane & 3) * 2;
        float4 xlo = *(const float4*)(X + (size_t)(ab * NN + kb) * 2);
        float4 xhi = *(const float4*)(X + (size_t)(ab * NN + kb + 8) * 2);
        int   row0 = slab * 16 + (lane >> 2);
        float li0 = -3.0f + (float)row0 * STEP;
        float li1 = -3.0f + (float)(row0 + 8) * STEP;
        float a, c2;
        uint4 v;
        a = li0 - xlo.x; c2 = li0 - xlo.z;
        v.x = pack_bf16(ex2f(a * a * EX2C), ex2f(c2 * c2 * EX2C));
        a = li1 - xlo.x; c2 = li1 - xlo.z;
        v.y = pack_bf16(ex2f(a * a * EX2C), ex2f(c2 * c2 * EX2C));
        a = li0 - xhi.x; c2 = li0 - xhi.z;
        v.z = pack_bf16(ex2f(a * a * EX2C), ex2f(c2 * c2 * EX2C));
        a = li1 - xhi.x; c2 = li1 - xhi.z;
        v.w = pack_bf16(ex2f(a * a * EX2C), ex2f(c2 * c2 * EX2C));
        ((uint4*)g_Aperm)[flat] = v;

        if (bx < 8) {                          // grid coords: 4096 points
            int p = bx * 512 + t;
            out[p * 2 + 0] = -3.0f + (float)(p >> 6) * STEP;
            out[p * 2 + 1] = -3.0f + (float)(p & 63) * STEP;
        }
    }
    __syncthreads();
    if (t == 0) { __threadfence(); atomicAdd(&g_arrive, 1); }

    // ===== Phase 1: build THIS group's Z half; 1 jl-pair item/thread =====
    {
        const float* yb = Y + (size_t)b * (NN * 8);
        int jlp   = tl & 1;
        int q     = (tl >> 1) & 3;
        int kstep = ks * 32 + (tl >> 3);
        int klo   = kstep * 16 + q * 2;

        float4 xA = *(const float4*)(X + (size_t)(b * NN + klo) * 2);
        float4 xB = *(const float4*)(X + (size_t)(b * NN + klo + 8) * 2);

        const float4* y0p = (const float4*)(yb + (size_t)klo * 8);
        float4 y0a = y0p[0],  y0b = y0p[1];
        float4 y1a = y0p[2],  y1b = y0p[3];
        float4 y8a = y0p[16], y8b = y0p[17];
        float4 y9a = y0p[18], y9b = y0p[19];

        float Y0[8] = {y0a.x, y0a.y, y0a.z, y0a.w, y0b.x, y0b.y, y0b.z, y0b.w};
        float Y1[8] = {y1a.x, y1a.y, y1a.z, y1a.w, y1b.x, y1b.y, y1b.z, y1b.w};
        float Y8[8] = {y8a.x, y8a.y, y8a.z, y8a.w, y8b.x, y8b.y, y8b.z, y8b.w};
        float Y9[8] = {y9a.x, y9a.y, y9a.z, y9a.w, y9b.x, y9b.y, y9b.z, y9b.w};

        uint2* zk = sZ + (size_t)kstep * 5 * 32 + q;
#pragma unroll
        for (int jv = 0; jv < 2; ++jv) {
            int jl = jlp * 2 + jv;
            float lj = -3.0f + (float)(jt * 4 + jl) * STEP;
            float dA0 = lj - xA.y, dA1 = lj - xA.w;
            float dB0 = lj - xB.y, dB1 = lj - xB.w;
            float e0 = ex2f(dA0 * dA0 * EX2C);
            float e1 = ex2f(dA1 * dA1 * EX2C);
            float e8 = ex2f(dB0 * dB0 * EX2C);
            float e9 = ex2f(dB1 * dB1 * EX2C);

            int nbase = jl * 10;
#pragma unroll
            for (int c = 0; c < 10; ++c) {
                int n  = nbase + c;
                int nc = n >> 3;
                int r  = n & 7;
                uint2 z;
                if (c == 0) {
                    z.x = pack_bf16(e0, e1);
                    z.y = pack_bf16(e8, e9);
                } else if (c == 9) {
                    z.x = 0u; z.y = 0u;
                } else {
                    z.x = pack_bf16(e0 * Y0[c - 1], e1 * Y1[c - 1]);
                    z.y = pack_bf16(e8 * Y8[c - 1], e9 * Y9[c - 1]);
                }
                zk[nc * 32 + r * 4] = z;
            }
        }
    }

    // ===== soft grid barrier: wait for all 256 A-slices =====
    if (t == 0) {
        while (atomicAdd(&g_arrive, 0) < 256) {}
        __threadfence();
    }
    __syncthreads();     // also publishes both groups' Z halves

    // ===== Phase 2: mma mainloop (chunked, 4 A frags) =====
    const int lane = tl & 31;
    const int wid  = tl >> 5;
    const int slab = wid & 3;
    const int nh   = wid >> 2;
    const int nc0  = nh * 3;
    const int ncnt = nh ? 2 : 3;

    float acc[3][4];
#pragma unroll
    for (int a = 0; a < 3; ++a)
#pragma unroll
        for (int r = 0; r < 4; ++r) acc[a][r] = 0.0f;

    const uint4* gA = (const uint4*)g_Aperm + (size_t)b * 8192 + ks * 4096
                      + slab * 32 + lane;
    const uint2* zb = sZ + (size_t)(ks * 32 * 5 + nc0) * 32 + lane;

#pragma unroll 2
    for (int ch = 0; ch < 8; ++ch) {
        uint4 af[4];
        uint2 zf[4][3];
#pragma unroll
        for (int kst = 0; kst < 4; ++kst)
            af[kst] = __ldg(gA + (ch * 4 + kst) * 128);
#pragma unroll
        for (int kst = 0; kst < 4; ++kst)
#pragma unroll
            for (int cc = 0; cc < 3; ++cc)
                if (cc < ncnt)
                    zf[kst][cc] = zb[((ch * 4 + kst) * 5 + cc) * 32];
#pragma unroll
        for (int kst = 0; kst < 4; ++kst)
#pragma unroll
            for (int cc = 0; cc < 3; ++cc)
                if (cc < ncnt)
                    MMA_BF16(acc[cc], af[kst], zf[kst][cc]);
    }

    // ===== epilogue: cross-group reduce + normalize + store =====
    __syncthreads();
    float* sD = (float*)sZ;

    if (ks == 1) {
#pragma unroll
        for (int cc = 0; cc < 3; ++cc) {
            if (cc < ncnt) {
                float4 v = make_float4(acc[cc][0], acc[cc][1], acc[cc][2], acc[cc][3]);
                *(float4*)(sD + (((nc0 + cc) * 4 + slab) * 32 + lane) * 4) = v;
            }
        }
    }
    __syncthreads();
    if (ks == 0) {
#pragma unroll
        for (int cc = 0; cc < 3; ++cc) {
            if (cc < ncnt) {
                float4* p4 = (float4*)(sD + (((nc0 + cc) * 4 + slab) * 32 + lane) * 4);
                float4 v = *p4;
                v.x += acc[cc][0]; v.y += acc[cc][1];
                v.z += acc[cc][2]; v.w += acc[cc][3];
                *p4 = v;
            }
        }
    }
    __syncthreads();

#pragma unroll
    for (int rep = 0; rep < 5; ++rep) {
        int o = t + rep * 512;
        if (o < 2304) {
            int i   = o / 36;
            int rem = o - i * 36;
            int j   = rem / 9;
            int c   = rem - j * 9;
            int sl = i >> 4, rr = i & 15, half = rr >> 3, r8 = rr & 7;
            int col  = j * 10 + c;
            int idx  = (((col >> 3) * 4 + sl) * 32 + r8 * 4 + ((col & 7) >> 1)) * 4
                       + half * 2 + (col & 1);
            int colD = j * 10;
            int idxD = (((colD >> 3) * 4 + sl) * 32 + r8 * 4 + ((colD & 7) >> 1)) * 4
                       + half * 2 + (colD & 1);
            float dens = sD[idxD];
            float v = (c == 0) ? dens : sD[idx] / (dens + 1e-6f);
            out[8192 + (size_t)(b * 4096 + i * 64 + jt * 4 + j) * 9 + c] = v;
        }
    }

    // ===== counter reset for graph replays (last CTA to finish) =====
    if (t == 0) {
        int d = atomicAdd(&g_done, 1);
        if (d == 255) { g_arrive = 0; g_done = 0; }
    }
}

extern "C" void kernel_launch(void* const* d_in, const int* in_sizes, int n_in,
                              void* d_out, int out_size)
{
    const float* X = (const float*)d_in[0];
    const float* Y = (const float*)d_in[1];
    float* out = (float*)d_out;

    const int zbytes = ZSLOTS * (int)sizeof(uint2);   // 81920
    cudaFuncSetAttribute(rkhs_fused_kernel,
                         cudaFuncAttributeMaxDynamicSharedMemorySize, zbytes);

    rkhs_fused_kernel<<<256, 512, zbytes>>>(X, Y, out);
}